// round 12
// baseline (speedup 1.0000x reference)
#include <cuda_runtime.h>
#include <cuda_bf16.h>
#include <math.h>

#define SUB   20
#define ENO   2000
#define INO   500
#define TD    20000
#define KTOT  2500
#define NQ    4
#define NTAPS 48

// ---------------- device scratch ----------------
// B matrix, transposed + bf16, quarter-padded: [c][q][k_local], k_local 0..511 (500..511 zero)
__device__ __align__(16) __nv_bfloat16 g_CtT[64][NQ + 1][512];
__device__ float g_inET[NQ][64 * TD];    // channel-major partial e results [q][c*TD + t]
__device__ float g_inIT[64 * TD];        // channel-major i results [c*TD + t]
__device__ float g_syn[60][TD];

__device__ __forceinline__ unsigned smem_u32(const void* p) {
    return (unsigned)__cvta_generic_to_shared(p);
}
__device__ __forceinline__ unsigned pack_bf2(float a, float b) {
    __nv_bfloat162 h = __floats2bfloat162_rn(a, b);
    return *(unsigned*)&h;
}
__device__ __forceinline__ float fast_tanh(float x) {
    float y;
    asm("tanh.approx.f32 %0, %1;" : "=f"(y) : "f"(x));
    return y;
}

// ---------------- kernel 1: prep (warp per column n, s -> lane) ----------------
__global__ __launch_bounds__(128) void prep_kernel(const float* __restrict__ u,
                                                   const float* __restrict__ v,
                                                   const float* __restrict__ cl,
                                                   float* __restrict__ out) {
    if (blockIdx.x == 0) {
        for (int idx = threadIdx.x; idx < 64 * (NQ + 1) * 12; idx += 128) {
            int c = idx / ((NQ + 1) * 12);
            int rem = idx % ((NQ + 1) * 12);
            int q = rem / 12, kl = 500 + rem % 12;
            g_CtT[c][q][kl] = __float2bfloat16(0.0f);
        }
    }
    int warp = threadIdx.x >> 5, lane = threadIdx.x & 31;
    int n = blockIdx.x * 4 + warp;
    if (n >= KTOT) return;
    int s = lane;
    bool act = (s < SUB);

    float c = act ? cl[s * KTOT + n] : -1e30f;
    float m = c;
#pragma unroll
    for (int o = 16; o; o >>= 1) m = fmaxf(m, __shfl_xor_sync(0xffffffffu, m, o));
    float e = act ? __expf(c - m) : 0.0f;
    float sum = e;
#pragma unroll
    for (int o = 16; o; o >>= 1) sum += __shfl_xor_sync(0xffffffffu, sum, o);
    float theta = e / sum;
    float ltheta = (c - m) - __logf(sum);

    float uu = act ? u[s * KTOT + n] : 0.5f;
    float vv = act ? v[s * KTOT + n] : 0.5f;
    float rz = act ? (ltheta - __logf(-__logf(uu))) : -1e30f;

    float best = rz; int bidx = s;
#pragma unroll
    for (int o = 16; o; o >>= 1) {
        float ob = __shfl_xor_sync(0xffffffffu, best, o);
        int   oi = __shfl_xor_sync(0xffffffffu, bidx, o);
        if (ob > best || (ob == best && oi < bidx)) { best = ob; bidx = oi; }
    }
    int k = bidx;
    float vk  = __shfl_sync(0xffffffffu, vv, k);
    float lvk = __logf(vk);

    if (act) {
        float hard = (s == k) ? 1.0f : 0.0f;
        float soft = 1.0f / (1.0f + __expf(-2.0f * rz)) + 1e-9f;
        float zb   = (s == k) ? -__logf(-__logf(vv))
                              : -__logf((-__logf(vv)) / theta - lvk);
        float szb  = 1.0f / (1.0f + __expf(-2.0f * zb)) + 1e-9f;
        out[ 60000 + s * KTOT + n] = theta;
        out[110000 + s * KTOT + n] = hard;
        out[160000 + s * KTOT + n] = soft;
        out[210000 + s * KTOT + n] = szb;
        int q = (n < 2000) ? (n / 500) : NQ;
        int kl = (n < 2000) ? (n % 500) : (n - 2000);
        g_CtT[s     ][q][kl] = __float2bfloat16(hard);
        g_CtT[20 + s][q][kl] = __float2bfloat16_rn(soft);
        g_CtT[40 + s][q][kl] = __float2bfloat16_rn(szb);
        if (s < 4) g_CtT[60 + s][q][kl] = __float2bfloat16(0.0f);
    }
}

// ---------------- kernel 2: bf16 GEMM, 256 threads / 8 warps (16 rows per warp) ----------------
#define BM 128

__global__ __launch_bounds__(256) void gemm_kernel(const float* __restrict__ Se,
                                                   const float* __restrict__ Si) {
    __shared__ __align__(16) unsigned char smem_raw[30720];
    __nv_bfloat16 (*As)[BM][40] = (__nv_bfloat16 (*)[BM][40])smem_raw;            // 20480 B
    __nv_bfloat16 (*Bt)[64][40] = (__nv_bfloat16 (*)[64][40])(smem_raw + 20480);  // 10240 B
    float* trans = (float*)smem_raw;                                              // 128x33 fl

    int q  = blockIdx.y;
    int t0 = blockIdx.x * BM;
    const float* A; int lda, k0;  float* outT;
    if (q < NQ) { A = Se; lda = ENO; k0 = q * 500; outT = g_inET[q]; }
    else        { A = Si; lda = INO; k0 = 0;       outT = g_inIT;    }

    int tid = threadIdx.x, warp = tid >> 5, lane = tid & 31;
    int qd = lane >> 2, r = lane & 3;
    int mW = warp * 16;

    float acc[8][4];
#pragma unroll
    for (int b = 0; b < 8; b++)
#pragma unroll
        for (int cc = 0; cc < 4; cc++) acc[b][cc] = 0.0f;

    // A staging mapping: 256 threads, 4 passes of 32 rows, warp covers 4 rows x 128B
    int arow_l = tid >> 3;          // 0..31 (+32 per pass)
    int akp4   = (tid & 7) * 4;     // float offset within 32-float chunk

    // ldmatrix source addresses (buffer 0 bases)
    const unsigned ABUF = BM * 40 * 2;
    const unsigned BBUF = 64 * 40 * 2;
    int a_row  = mW + (lane & 15);
    int a_koff = (lane >> 4) * 8;
    unsigned a_base0 = smem_u32(&As[0][a_row][a_koff]);
    int g2 = lane >> 3;
    int b_row  = (g2 >> 1) * 8 + (lane & 7);
    int b_koff = (g2 & 1) * 8;
    unsigned b_base0 = smem_u32(&Bt[0][b_row][b_koff]);

    int brow_st = tid >> 2, buidx = tid & 3;   // B staging: 64 rows x 4 uint4, 1 per thread

    uint2 aS2[4]; uint4 bS;

#define LOAD_CHUNK(KC)                                                          \
    {                                                                           \
        int kb = (KC) * 32;                                                     \
        int k8 = kb + akp4;                                                     \
        _Pragma("unroll")                                                       \
        for (int p = 0; p < 4; p++) {                                           \
            int row = arow_l + p * 32;                                          \
            int tg = t0 + row;                                                  \
            float4 f = make_float4(0.f, 0.f, 0.f, 0.f);                         \
            if (tg < TD && k8 < 500)                                            \
                f = *(const float4*)&A[(size_t)tg * lda + k0 + k8];             \
            aS2[p].x = pack_bf2(f.x, f.y); aS2[p].y = pack_bf2(f.z, f.w);       \
        }                                                                       \
        bS = *(const uint4*)&g_CtT[brow_st][q][kb + buidx * 8];                 \
    }

#define STORE_CHUNK(BUF)                                                        \
    {                                                                           \
        _Pragma("unroll")                                                       \
        for (int p = 0; p < 4; p++)                                             \
            *(uint2*)&As[BUF][arow_l + p * 32][akp4] = aS2[p];                  \
        *(uint4*)&Bt[BUF][brow_st][buidx * 8] = bS;                             \
    }

    LOAD_CHUNK(0);
    STORE_CHUNK(0);
    __syncthreads();

    for (int kc = 0; kc < 16; kc++) {
        int nb = kc & 1;
        bool more = (kc + 1 < 16);
        if (more) LOAD_CHUNK(kc + 1);

        unsigned a_addr0 = a_base0 + nb * ABUF;
        unsigned b_addr  = b_base0 + nb * BBUF;
#pragma unroll
        for (int kk = 0; kk < 32; kk += 16) {
            unsigned a0[4], b[8][2];
            asm volatile("ldmatrix.sync.aligned.m8n8.x4.shared.b16 {%0,%1,%2,%3}, [%4];"
                         : "=r"(a0[0]), "=r"(a0[1]), "=r"(a0[2]), "=r"(a0[3])
                         : "r"(a_addr0 + kk * 2));
#pragma unroll
            for (int p = 0; p < 4; p++) {
                asm volatile("ldmatrix.sync.aligned.m8n8.x4.shared.b16 {%0,%1,%2,%3}, [%4];"
                             : "=r"(b[2 * p][0]), "=r"(b[2 * p][1]),
                               "=r"(b[2 * p + 1][0]), "=r"(b[2 * p + 1][1])
                             : "r"(b_addr + p * (16 * 40 * 2) + kk * 2));
            }
#pragma unroll
            for (int nT = 0; nT < 8; nT++) {
                asm volatile(
                    "mma.sync.aligned.m16n8k16.row.col.f32.bf16.bf16.f32 "
                    "{%0,%1,%2,%3}, {%4,%5,%6,%7}, {%8,%9}, {%0,%1,%2,%3};"
                    : "+f"(acc[nT][0]), "+f"(acc[nT][1]),
                      "+f"(acc[nT][2]), "+f"(acc[nT][3])
                    : "r"(a0[0]), "r"(a0[1]), "r"(a0[2]), "r"(a0[3]),
                      "r"(b[nT][0]), "r"(b[nT][1]));
            }
        }
        if (more) STORE_CHUNK(1 - nb);
        __syncthreads();
    }

    // ---- transposed epilogue: smem transpose, coalesced channel-major STG ----
#pragma unroll
    for (int h = 0; h < 2; h++) {
        __syncthreads();
#pragma unroll
        for (int j = 0; j < 4; j++) {
            int nT = h * 4 + j;
            int row = mW + qd;
            int clc = j * 8 + 2 * r;
            trans[row * 33 + clc]           = acc[nT][0];
            trans[row * 33 + clc + 1]       = acc[nT][1];
            trans[(row + 8) * 33 + clc]     = acc[nT][2];
            trans[(row + 8) * 33 + clc + 1] = acc[nT][3];
        }
        __syncthreads();
#pragma unroll
        for (int rnd = 0; rnd < 16; rnd++) {
            int clc = warp * 4 + (rnd >> 2);
            int tg  = rnd & 3;
            int tt  = t0 + tg * 32 + lane;
            if (tt < TD)
                outT[(h * 32 + clc) * TD + tt] = trans[(tg * 32 + lane) * 33 + clc];
        }
    }
}

// ---------------- kernel 3: 48-tap causal FIR per channel ----------------
#define TT 1024

__global__ __launch_bounds__(256) void fir_kernel(const float* __restrict__ Wsyn,
                                                  const float* __restrict__ Tausyn,
                                                  const float* __restrict__ Dsyn) {
    __shared__ __align__(16) float xe[4 + TT + NTAPS + 4];
    __shared__ __align__(16) float xi[4 + TT + NTAPS + 4];
    __shared__ __align__(16) float ke[NTAPS + 4];
    __shared__ __align__(16) float ki[NTAPS + 4];
    int p  = blockIdx.y;
    int s  = p % 20;
    int c  = p;
    int t0 = blockIdx.x * TT;
    int tid = threadIdx.x;

    if (tid < NTAPS + 4) {
        float kv0 = 0.f, kv1 = 0.f;
        if (tid < NTAPS) {
            float itau0 = expf(-Tausyn[s * 2 + 0]);
            float itau1 = expf(-Tausyn[s * 2 + 1]);
            float d0 = expf(Dsyn[s * 2 + 0]);
            float d1 = expf(Dsyn[s * 2 + 1]);
            float w0 = Wsyn[s * 2 + 0], w1 = Wsyn[s * 2 + 1];
            float tt_ = fmaxf((float)tid - d0, 0.0f) * itau0;
            kv0 = tt_ * expf(-tt_) * w0;
            tt_ = fmaxf((float)tid - d1, 0.0f) * itau1;
            kv1 = tt_ * expf(-tt_) * w1;
        }
        ke[tid] = kv0; ki[tid] = kv1;
    }
    const float* e0 = &g_inET[0][c * TD];
    const float* e1 = &g_inET[1][c * TD];
    const float* e2 = &g_inET[2][c * TD];
    const float* e3 = &g_inET[3][c * TD];
    const float* ii = &g_inIT[c * TD];
    for (int idx = tid; idx < TT + NTAPS; idx += 256) {
        int g = t0 - NTAPS + idx;
        float ve = 0.f, vi = 0.f;
        if (g >= 0 && g < TD) {
            ve = e0[g] + e1[g] + e2[g] + e3[g];
            vi = ii[g];
        }
        xe[4 + idx] = ve;
        xi[4 + idx] = vi;
    }
    if (tid < 4) { xe[tid] = 0.f; xi[tid] = 0.f; }
    __syncthreads();

    float acc0 = 0.f, acc1 = 0.f, acc2 = 0.f, acc3 = 0.f;
    int pos = NTAPS + tid * 4;
    {
        float w[8];
        *(float4*)&w[4] = *(float4*)&xe[4 + pos];
#pragma unroll 6
        for (int tau = 0; tau <= NTAPS - 4; tau += 4) {
            *(float4*)&w[0] = *(float4*)&xe[pos - tau];
            float4 kk = *(float4*)&ke[tau];
            acc0 += kk.x * w[4]; acc1 += kk.x * w[5]; acc2 += kk.x * w[6]; acc3 += kk.x * w[7];
            acc0 += kk.y * w[3]; acc1 += kk.y * w[4]; acc2 += kk.y * w[5]; acc3 += kk.y * w[6];
            acc0 += kk.z * w[2]; acc1 += kk.z * w[3]; acc2 += kk.z * w[4]; acc3 += kk.z * w[5];
            acc0 += kk.w * w[1]; acc1 += kk.w * w[2]; acc2 += kk.w * w[3]; acc3 += kk.w * w[4];
            w[4] = w[0]; w[5] = w[1]; w[6] = w[2]; w[7] = w[3];
        }
    }
    {
        float w[8];
        *(float4*)&w[4] = *(float4*)&xi[4 + pos];
#pragma unroll 6
        for (int tau = 0; tau <= NTAPS - 4; tau += 4) {
            *(float4*)&w[0] = *(float4*)&xi[pos - tau];
            float4 kk = *(float4*)&ki[tau];
            acc0 += kk.x * w[4]; acc1 += kk.x * w[5]; acc2 += kk.x * w[6]; acc3 += kk.x * w[7];
            acc0 += kk.y * w[3]; acc1 += kk.y * w[4]; acc2 += kk.y * w[5]; acc3 += kk.y * w[6];
            acc0 += kk.z * w[2]; acc1 += kk.z * w[3]; acc2 += kk.z * w[4]; acc3 += kk.z * w[5];
            acc0 += kk.w * w[1]; acc1 += kk.w * w[2]; acc2 += kk.w * w[3]; acc3 += kk.w * w[4];
            w[4] = w[0]; w[5] = w[1]; w[6] = w[2]; w[7] = w[3];
        }
    }
    int t = t0 + tid * 4;
    if (t < TD)
        *(float4*)&g_syn[p][t] = make_float4(acc0, acc1, acc2, acc3);
}

// ---------------- kernel 4: subunit tree + output (tanh.approx) ----------------
__global__ void tree_kernel(const float* __restrict__ Wsub, const float* __restrict__ Vo,
                            float* __restrict__ out) {
    int t = blockIdx.x * blockDim.x + threadIdx.x;
    int var = blockIdx.y;
    if (t >= TD) return;
    float W[20];
#pragma unroll
    for (int s = 0; s < 20; s++) W[s] = Wsub[s];
    float vo = Vo[0];
    float sub[20];
#pragma unroll
    for (int s = 19; s >= 10; s--) sub[s] = fast_tanh(g_syn[var * 20 + s][t]);
    sub[9] = fast_tanh(g_syn[var * 20 + 9][t] + sub[19] * W[19]);
#pragma unroll
    for (int s = 8; s >= 0; s--)
        sub[s] = fast_tanh(g_syn[var * 20 + s][t]
                           + sub[2 * s + 1] * W[2 * s + 1]
                           + sub[2 * s + 2] * W[2 * s + 2]);
    out[var * TD + t] = sub[0] * W[0] + vo;
}

// ---------------- launch ----------------
extern "C" void kernel_launch(void* const* d_in, const int* in_sizes, int n_in,
                              void* d_out, int out_size) {
    const float* Se   = (const float*)d_in[0];
    const float* Si   = (const float*)d_in[1];
    const float* u    = (const float*)d_in[2];
    const float* v    = (const float*)d_in[3];
    const float* Wsyn = (const float*)d_in[4];
    const float* Tau  = (const float*)d_in[5];
    const float* Dlt  = (const float*)d_in[6];
    const float* Wsub = (const float*)d_in[7];
    const float* Vo   = (const float*)d_in[8];
    const float* Cl   = (const float*)d_in[10];
    float* out = (float*)d_out;

    prep_kernel<<<(KTOT + 3) / 4, 128>>>(u, v, Cl, out);
    dim3 gg((TD + BM - 1) / BM, NQ + 1);       // (157, 5)
    gemm_kernel<<<gg, 256>>>(Se, Si);
    dim3 gf((TD + TT - 1) / TT, 60);
    fir_kernel<<<gf, 256>>>(Wsyn, Tau, Dlt);
    dim3 gt((TD + 255) / 256, 3);
    tree_kernel<<<gt, 256>>>(Wsub, Vo, out);
}

// round 15
// speedup vs baseline: 1.0402x; 1.0402x over previous
#include <cuda_runtime.h>
#include <cuda_bf16.h>
#include <stdint.h>
#include <math.h>

#define SUB   20
#define ENO   2000
#define INO   500
#define TD    20000
#define KTOT  2500
#define NQ    4
#define NTAPS 48

// ---------------- device scratch ----------------
// B matrix, transposed + bf16, quarter-padded: [c][q][k_local], k_local 0..511 (500..511 zero)
__device__ __align__(16) __nv_bfloat16 g_CtT[64][NQ + 1][512];
__device__ float g_inET[NQ][64 * TD];    // channel-major partial e results [q][c*TD + t]
__device__ float g_inIT[64 * TD];        // channel-major i results [c*TD + t]
__device__ float g_syn[60][TD];

__device__ __forceinline__ unsigned smem_u32(const void* p) {
    return (unsigned)__cvta_generic_to_shared(p);
}
__device__ __forceinline__ unsigned pack_bf2(float a, float b) {
    __nv_bfloat162 h = __floats2bfloat162_rn(a, b);
    return *(unsigned*)&h;
}
__device__ __forceinline__ float fast_tanh(float x) {
    float y;
    asm("tanh.approx.f32 %0, %1;" : "=f"(y) : "f"(x));
    return y;
}

// ---------------- kernel 1: prep (warp per column n, s -> lane) ----------------
__global__ __launch_bounds__(128) void prep_kernel(const float* __restrict__ u,
                                                   const float* __restrict__ v,
                                                   const float* __restrict__ cl,
                                                   float* __restrict__ out) {
    if (blockIdx.x == 0) {
        for (int idx = threadIdx.x; idx < 64 * (NQ + 1) * 12; idx += 128) {
            int c = idx / ((NQ + 1) * 12);
            int rem = idx % ((NQ + 1) * 12);
            int q = rem / 12, kl = 500 + rem % 12;
            g_CtT[c][q][kl] = __float2bfloat16(0.0f);
        }
    }
    int warp = threadIdx.x >> 5, lane = threadIdx.x & 31;
    int n = blockIdx.x * 4 + warp;
    if (n >= KTOT) return;
    int s = lane;
    bool act = (s < SUB);

    float c = act ? cl[s * KTOT + n] : -1e30f;
    float m = c;
#pragma unroll
    for (int o = 16; o; o >>= 1) m = fmaxf(m, __shfl_xor_sync(0xffffffffu, m, o));
    float e = act ? __expf(c - m) : 0.0f;
    float sum = e;
#pragma unroll
    for (int o = 16; o; o >>= 1) sum += __shfl_xor_sync(0xffffffffu, sum, o);
    float theta = e / sum;
    float ltheta = (c - m) - __logf(sum);

    float uu = act ? u[s * KTOT + n] : 0.5f;
    float vv = act ? v[s * KTOT + n] : 0.5f;
    float rz = act ? (ltheta - __logf(-__logf(uu))) : -1e30f;

    float best = rz; int bidx = s;
#pragma unroll
    for (int o = 16; o; o >>= 1) {
        float ob = __shfl_xor_sync(0xffffffffu, best, o);
        int   oi = __shfl_xor_sync(0xffffffffu, bidx, o);
        if (ob > best || (ob == best && oi < bidx)) { best = ob; bidx = oi; }
    }
    int k = bidx;
    float vk  = __shfl_sync(0xffffffffu, vv, k);
    float lvk = __logf(vk);

    if (act) {
        float hard = (s == k) ? 1.0f : 0.0f;
        float soft = 1.0f / (1.0f + __expf(-2.0f * rz)) + 1e-9f;
        float zb   = (s == k) ? -__logf(-__logf(vv))
                              : -__logf((-__logf(vv)) / theta - lvk);
        float szb  = 1.0f / (1.0f + __expf(-2.0f * zb)) + 1e-9f;
        out[ 60000 + s * KTOT + n] = theta;
        out[110000 + s * KTOT + n] = hard;
        out[160000 + s * KTOT + n] = soft;
        out[210000 + s * KTOT + n] = szb;
        int q = (n < 2000) ? (n / 500) : NQ;
        int kl = (n < 2000) ? (n % 500) : (n - 2000);
        g_CtT[s     ][q][kl] = __float2bfloat16(hard);
        g_CtT[20 + s][q][kl] = __float2bfloat16_rn(soft);
        g_CtT[40 + s][q][kl] = __float2bfloat16_rn(szb);
        if (s < 4) g_CtT[60 + s][q][kl] = __float2bfloat16(0.0f);
    }
}

// ---------------- kernel 2: bf16 GEMM (round-11 structure, unchanged) ----------------
#define BM 128

__global__ __launch_bounds__(128) void gemm_kernel(const float* __restrict__ Se,
                                                   const float* __restrict__ Si) {
    __shared__ __align__(16) unsigned char smem_raw[30720];
    __nv_bfloat16 (*As)[BM][40] = (__nv_bfloat16 (*)[BM][40])smem_raw;            // 20480 B
    __nv_bfloat16 (*Bt)[64][40] = (__nv_bfloat16 (*)[64][40])(smem_raw + 20480);  // 10240 B
    float* trans = (float*)smem_raw;                                              // 128x33 fl

    int q  = blockIdx.y;
    int t0 = blockIdx.x * BM;
    const float* A; int lda, k0;  float* outT;
    if (q < NQ) { A = Se; lda = ENO; k0 = q * 500; outT = g_inET[q]; }
    else        { A = Si; lda = INO; k0 = 0;       outT = g_inIT;    }

    int tid = threadIdx.x, warp = tid >> 5, lane = tid & 31;
    int qd = lane >> 2, r = lane & 3;
    int mW = warp * 32;

    float acc[2][8][4];
#pragma unroll
    for (int a = 0; a < 2; a++)
#pragma unroll
        for (int b = 0; b < 8; b++)
#pragma unroll
            for (int cc = 0; cc < 4; cc++) acc[a][b][cc] = 0.0f;

    // A staging mapping: coalesced (warp covers 4 rows x 128B contiguous)
    int arow_l = tid >> 3;          // 0..15 (+16 per pass)
    int akp4   = (tid & 7) * 4;     // float offset within 32-float chunk

    const unsigned ABUF = BM * 40 * 2;
    const unsigned BBUF = 64 * 40 * 2;
    int a_row  = mW + (lane & 15);
    int a_koff = (lane >> 4) * 8;
    unsigned a_base0 = smem_u32(&As[0][a_row][a_koff]);
    int g2 = lane >> 3;
    int b_row  = (g2 >> 1) * 8 + (lane & 7);
    int b_koff = (g2 & 1) * 8;
    unsigned b_base0 = smem_u32(&Bt[0][b_row][b_koff]);

    int brow_st = tid >> 2, buidx = tid & 3;

    uint2 aS2[8]; uint4 bS[2];

#define LOAD_CHUNK(KC)                                                          \
    {                                                                           \
        int kb = (KC) * 32;                                                     \
        int k8 = kb + akp4;                                                     \
        _Pragma("unroll")                                                       \
        for (int p = 0; p < 8; p++) {                                           \
            int row = arow_l + p * 16;                                          \
            int tg = t0 + row;                                                  \
            float4 f = make_float4(0.f, 0.f, 0.f, 0.f);                         \
            if (tg < TD && k8 < 500)                                            \
                f = *(const float4*)&A[(size_t)tg * lda + k0 + k8];             \
            aS2[p].x = pack_bf2(f.x, f.y); aS2[p].y = pack_bf2(f.z, f.w);       \
        }                                                                       \
        bS[0] = *(const uint4*)&g_CtT[brow_st][q][kb + buidx * 8];              \
        bS[1] = *(const uint4*)&g_CtT[brow_st + 32][q][kb + buidx * 8];         \
    }

#define STORE_CHUNK(BUF)                                                        \
    {                                                                           \
        _Pragma("unroll")                                                       \
        for (int p = 0; p < 8; p++)                                             \
            *(uint2*)&As[BUF][arow_l + p * 16][akp4] = aS2[p];                  \
        *(uint4*)&Bt[BUF][brow_st][buidx * 8] = bS[0];                          \
        *(uint4*)&Bt[BUF][brow_st + 32][buidx * 8] = bS[1];                     \
    }

    LOAD_CHUNK(0);
    STORE_CHUNK(0);
    __syncthreads();

    for (int kc = 0; kc < 16; kc++) {
        int nb = kc & 1;
        bool more = (kc + 1 < 16);
        if (more) LOAD_CHUNK(kc + 1);

        unsigned a_addr0 = a_base0 + nb * ABUF;
        unsigned a_addr1 = a_addr0 + 16 * 40 * 2;
        unsigned b_addr  = b_base0 + nb * BBUF;
#pragma unroll
        for (int kk = 0; kk < 32; kk += 16) {
            unsigned a0[4], a1[4], b[8][2];
            asm volatile("ldmatrix.sync.aligned.m8n8.x4.shared.b16 {%0,%1,%2,%3}, [%4];"
                         : "=r"(a0[0]), "=r"(a0[1]), "=r"(a0[2]), "=r"(a0[3])
                         : "r"(a_addr0 + kk * 2));
            asm volatile("ldmatrix.sync.aligned.m8n8.x4.shared.b16 {%0,%1,%2,%3}, [%4];"
                         : "=r"(a1[0]), "=r"(a1[1]), "=r"(a1[2]), "=r"(a1[3])
                         : "r"(a_addr1 + kk * 2));
#pragma unroll
            for (int p = 0; p < 4; p++) {
                asm volatile("ldmatrix.sync.aligned.m8n8.x4.shared.b16 {%0,%1,%2,%3}, [%4];"
                             : "=r"(b[2 * p][0]), "=r"(b[2 * p][1]),
                               "=r"(b[2 * p + 1][0]), "=r"(b[2 * p + 1][1])
                             : "r"(b_addr + p * (16 * 40 * 2) + kk * 2));
            }
#pragma unroll
            for (int nT = 0; nT < 8; nT++) {
                asm volatile(
                    "mma.sync.aligned.m16n8k16.row.col.f32.bf16.bf16.f32 "
                    "{%0,%1,%2,%3}, {%4,%5,%6,%7}, {%8,%9}, {%0,%1,%2,%3};"
                    : "+f"(acc[0][nT][0]), "+f"(acc[0][nT][1]),
                      "+f"(acc[0][nT][2]), "+f"(acc[0][nT][3])
                    : "r"(a0[0]), "r"(a0[1]), "r"(a0[2]), "r"(a0[3]),
                      "r"(b[nT][0]), "r"(b[nT][1]));
                asm volatile(
                    "mma.sync.aligned.m16n8k16.row.col.f32.bf16.bf16.f32 "
                    "{%0,%1,%2,%3}, {%4,%5,%6,%7}, {%8,%9}, {%0,%1,%2,%3};"
                    : "+f"(acc[1][nT][0]), "+f"(acc[1][nT][1]),
                      "+f"(acc[1][nT][2]), "+f"(acc[1][nT][3])
                    : "r"(a1[0]), "r"(a1[1]), "r"(a1[2]), "r"(a1[3]),
                      "r"(b[nT][0]), "r"(b[nT][1]));
            }
        }
        if (more) STORE_CHUNK(1 - nb);
        __syncthreads();
    }

    // ---- transposed epilogue: smem transpose, coalesced channel-major STG ----
#pragma unroll
    for (int h = 0; h < 2; h++) {
        __syncthreads();
#pragma unroll
        for (int tM = 0; tM < 2; tM++)
#pragma unroll
            for (int j = 0; j < 4; j++) {
                int nT = h * 4 + j;
                int row = mW + tM * 16 + qd;
                int clc = j * 8 + 2 * r;
                trans[row * 33 + clc]           = acc[tM][nT][0];
                trans[row * 33 + clc + 1]       = acc[tM][nT][1];
                trans[(row + 8) * 33 + clc]     = acc[tM][nT][2];
                trans[(row + 8) * 33 + clc + 1] = acc[tM][nT][3];
            }
        __syncthreads();
#pragma unroll
        for (int rnd = 0; rnd < 32; rnd++) {
            int clc = warp * 8 + (rnd >> 2);
            int tg  = rnd & 3;
            int tt  = t0 + tg * 32 + lane;
            if (tt < TD)
                outT[(h * 32 + clc) * TD + tt] = trans[(tg * 32 + lane) * 33 + clc];
        }
    }
}

// ---------------- kernel 3: 48-tap causal FIR per channel (float4 staging) ----------------
#define TT 1024

__global__ __launch_bounds__(256) void fir_kernel(const float* __restrict__ Wsyn,
                                                  const float* __restrict__ Tausyn,
                                                  const float* __restrict__ Dsyn) {
    __shared__ __align__(16) float xe[4 + TT + NTAPS + 4];
    __shared__ __align__(16) float xi[4 + TT + NTAPS + 4];
    __shared__ __align__(16) float ke[NTAPS + 4];
    __shared__ __align__(16) float ki[NTAPS + 4];
    int p  = blockIdx.y;
    int s  = p % 20;
    int c  = p;
    int t0 = blockIdx.x * TT;
    int tid = threadIdx.x;

    if (tid < NTAPS + 4) {
        float kv0 = 0.f, kv1 = 0.f;
        if (tid < NTAPS) {
            float itau0 = expf(-Tausyn[s * 2 + 0]);
            float itau1 = expf(-Tausyn[s * 2 + 1]);
            float d0 = expf(Dsyn[s * 2 + 0]);
            float d1 = expf(Dsyn[s * 2 + 1]);
            float w0 = Wsyn[s * 2 + 0], w1 = Wsyn[s * 2 + 1];
            float tt_ = fmaxf((float)tid - d0, 0.0f) * itau0;
            kv0 = tt_ * expf(-tt_) * w0;
            tt_ = fmaxf((float)tid - d1, 0.0f) * itau1;
            kv1 = tt_ * expf(-tt_) * w1;
        }
        ke[tid] = kv0; ki[tid] = kv1;
    }
    const float* e0 = &g_inET[0][c * TD];
    const float* e1 = &g_inET[1][c * TD];
    const float* e2 = &g_inET[2][c * TD];
    const float* e3 = &g_inET[3][c * TD];
    const float* ii = &g_inIT[c * TD];
    // float4 staging: (TT+NTAPS)/4 = 268 vector slots, g base t0-NTAPS is 4-aligned
    for (int v4 = tid; v4 < (TT + NTAPS) / 4; v4 += 256) {
        int g = t0 - NTAPS + v4 * 4;
        float4 ve, vi;
        if (g >= 0 && g + 3 < TD) {
            float4 a0 = *(const float4*)&e0[g];
            float4 a1 = *(const float4*)&e1[g];
            float4 a2 = *(const float4*)&e2[g];
            float4 a3 = *(const float4*)&e3[g];
            ve = make_float4(a0.x + a1.x + a2.x + a3.x, a0.y + a1.y + a2.y + a3.y,
                             a0.z + a1.z + a2.z + a3.z, a0.w + a1.w + a2.w + a3.w);
            vi = *(const float4*)&ii[g];
        } else {
            float t4[4], u4[4];
#pragma unroll
            for (int j = 0; j < 4; j++) {
                int gg = g + j;
                if (gg >= 0 && gg < TD) {
                    t4[j] = e0[gg] + e1[gg] + e2[gg] + e3[gg];
                    u4[j] = ii[gg];
                } else { t4[j] = 0.f; u4[j] = 0.f; }
            }
            ve = make_float4(t4[0], t4[1], t4[2], t4[3]);
            vi = make_float4(u4[0], u4[1], u4[2], u4[3]);
        }
        *(float4*)&xe[4 + v4 * 4] = ve;
        *(float4*)&xi[4 + v4 * 4] = vi;
    }
    if (tid < 4) { xe[tid] = 0.f; xi[tid] = 0.f; }
    __syncthreads();

    float acc0 = 0.f, acc1 = 0.f, acc2 = 0.f, acc3 = 0.f;
    int pos = NTAPS + tid * 4;
    {
        float w[8];
        *(float4*)&w[4] = *(float4*)&xe[4 + pos];
#pragma unroll 6
        for (int tau = 0; tau <= NTAPS - 4; tau += 4) {
            *(float4*)&w[0] = *(float4*)&xe[pos - tau];
            float4 kk = *(float4*)&ke[tau];
            acc0 += kk.x * w[4]; acc1 += kk.x * w[5]; acc2 += kk.x * w[6]; acc3 += kk.x * w[7];
            acc0 += kk.y * w[3]; acc1 += kk.y * w[4]; acc2 += kk.y * w[5]; acc3 += kk.y * w[6];
            acc0 += kk.z * w[2]; acc1 += kk.z * w[3]; acc2 += kk.z * w[4]; acc3 += kk.z * w[5];
            acc0 += kk.w * w[1]; acc1 += kk.w * w[2]; acc2 += kk.w * w[3]; acc3 += kk.w * w[4];
            w[4] = w[0]; w[5] = w[1]; w[6] = w[2]; w[7] = w[3];
        }
    }
    {
        float w[8];
        *(float4*)&w[4] = *(float4*)&xi[4 + pos];
#pragma unroll 6
        for (int tau = 0; tau <= NTAPS - 4; tau += 4) {
            *(float4*)&w[0] = *(float4*)&xi[pos - tau];
            float4 kk = *(float4*)&ki[tau];
            acc0 += kk.x * w[4]; acc1 += kk.x * w[5]; acc2 += kk.x * w[6]; acc3 += kk.x * w[7];
            acc0 += kk.y * w[3]; acc1 += kk.y * w[4]; acc2 += kk.y * w[5]; acc3 += kk.y * w[6];
            acc0 += kk.z * w[2]; acc1 += kk.z * w[3]; acc2 += kk.z * w[4]; acc3 += kk.z * w[5];
            acc0 += kk.w * w[1]; acc1 += kk.w * w[2]; acc2 += kk.w * w[3]; acc3 += kk.w * w[4];
            w[4] = w[0]; w[5] = w[1]; w[6] = w[2]; w[7] = w[3];
        }
    }
    int t = t0 + tid * 4;
    if (t < TD)
        *(float4*)&g_syn[p][t] = make_float4(acc0, acc1, acc2, acc3);
}

// ---------------- kernel 4: subunit tree, all-60 upfront loads, 3 vars/thread ----------------
__global__ __launch_bounds__(256) void tree_kernel(const float* __restrict__ Wsub,
                                                   const float* __restrict__ Vo,
                                                   float* __restrict__ out) {
    int t = blockIdx.x * blockDim.x + threadIdx.x;
    if (t >= TD) return;
    float g[60];
#pragma unroll
    for (int p = 0; p < 60; p++) g[p] = g_syn[p][t];   // 60 independent LDGs, deep MLP
    float W[20];
#pragma unroll
    for (int s = 0; s < 20; s++) W[s] = Wsub[s];
    float vo = Vo[0];
#pragma unroll
    for (int var = 0; var < 3; var++) {
        float sub[20];
#pragma unroll
        for (int s = 19; s >= 10; s--) sub[s] = fast_tanh(g[var * 20 + s]);
        sub[9] = fast_tanh(g[var * 20 + 9] + sub[19] * W[19]);
#pragma unroll
        for (int s = 8; s >= 0; s--)
            sub[s] = fast_tanh(g[var * 20 + s]
                               + sub[2 * s + 1] * W[2 * s + 1]
                               + sub[2 * s + 2] * W[2 * s + 2]);
        out[var * TD + t] = sub[0] * W[0] + vo;
    }
}

// ---------------- launch ----------------
extern "C" void kernel_launch(void* const* d_in, const int* in_sizes, int n_in,
                              void* d_out, int out_size) {
    const float* Se   = (const float*)d_in[0];
    const float* Si   = (const float*)d_in[1];
    const float* u    = (const float*)d_in[2];
    const float* v    = (const float*)d_in[3];
    const float* Wsyn = (const float*)d_in[4];
    const float* Tau  = (const float*)d_in[5];
    const float* Dlt  = (const float*)d_in[6];
    const float* Wsub = (const float*)d_in[7];
    const float* Vo   = (const float*)d_in[8];
    const float* Cl   = (const float*)d_in[10];
    float* out = (float*)d_out;

    prep_kernel<<<(KTOT + 3) / 4, 128>>>(u, v, Cl, out);
    dim3 gg((TD + BM - 1) / BM, NQ + 1);       // (157, 5)
    gemm_kernel<<<gg, 128>>>(Se, Si);
    dim3 gf((TD + TT - 1) / TT, 60);
    fir_kernel<<<gf, 256>>>(Wsyn, Tau, Dlt);
    tree_kernel<<<(TD + 255) / 256, 256>>>(Wsub, Vo, out);
}